// round 3
// baseline (speedup 1.0000x reference)
#include <cuda_runtime.h>
#include <math.h>

#define N_NODES 30000
#define N_EDGES 60000
#define FEAT    256
#define HID     1024
#define OUT_DIM 256
#define RANK    64

// ---------------- scratch (static device globals; no runtime allocation) ----
__device__ float g_emb_new [(size_t)N_NODES * RANK];
__device__ float g_hid     [(size_t)N_NODES * HID];
__device__ float g_emb_new2[(size_t)N_NODES * OUT_DIM];
__device__ float g_acc     [(size_t)N_NODES * OUT_DIM];

__device__ __forceinline__ float tanh_fast(float x)
{
    float y;
    asm("tanh.approx.f32 %0, %1;" : "=f"(y) : "f"(x));
    return y;
}

// ========== 128x128x16 SGEMM, 8x8 reg tile, double-buffered smem ============
// C = act(A @ W[:K] + wrow + bias); A: MxK row-major, W: (K(+1))xN row-major.
#define BM 128
#define BN 128
#define BK 16

__global__ __launch_bounds__(256) void gemm128_kernel(
    const float* __restrict__ A, const float* __restrict__ W,
    const float* __restrict__ bias, const float* __restrict__ wrow,
    float* __restrict__ C, int M, int N, int K, int do_relu)
{
    __shared__ float As[2][BK][BM + 4];
    __shared__ float Bs[2][BK][BN];
    const int tid = threadIdx.x;
    const int tx  = tid & 15;           // 8 output cols each
    const int ty  = tid >> 4;           // 8 output rows each
    const int m0  = blockIdx.y * BM;
    const int n0  = blockIdx.x * BN;

    const int arow = tid >> 2;          // 0..63 (two passes of 64 rows)
    const int acol = (tid & 3) << 2;    // 0,4,8,12
    const int brow = tid >> 5;          // 0..7 (two passes of 8 rows)
    const int bcol = (tid & 31) << 2;   // 0..124

    float acc[8][8];
#pragma unroll
    for (int i = 0; i < 8; i++)
#pragma unroll
        for (int j = 0; j < 8; j++) acc[i][j] = 0.f;

    float4 pa[2], pb[2];

    // --- prefetch tile 0 into registers ---
#pragma unroll
    for (int p = 0; p < 2; p++) {
        const int r = arow + p * 64;
        pa[p] = make_float4(0.f, 0.f, 0.f, 0.f);
        if (m0 + r < M)
            pa[p] = *(const float4*)(A + (size_t)(m0 + r) * K + acol);
        pb[p] = *(const float4*)(W + (size_t)(brow + p * 8) * N + n0 + bcol);
    }
    // store tile 0
#pragma unroll
    for (int p = 0; p < 2; p++) {
        const int r = arow + p * 64;
        As[0][acol + 0][r] = pa[p].x;
        As[0][acol + 1][r] = pa[p].y;
        As[0][acol + 2][r] = pa[p].z;
        As[0][acol + 3][r] = pa[p].w;
        *(float4*)&Bs[0][brow + p * 8][bcol] = pb[p];
    }
    __syncthreads();

    int cur = 0;
    for (int k0 = 0; k0 < K; k0 += BK) {
        const bool more = (k0 + BK) < K;
        // issue next-tile gmem loads early (latency overlapped with compute)
        if (more) {
            const int kn = k0 + BK;
#pragma unroll
            for (int p = 0; p < 2; p++) {
                const int r = arow + p * 64;
                pa[p] = make_float4(0.f, 0.f, 0.f, 0.f);
                if (m0 + r < M)
                    pa[p] = *(const float4*)(A + (size_t)(m0 + r) * K + kn + acol);
                pb[p] = *(const float4*)(W + (size_t)(kn + brow + p * 8) * N + n0 + bcol);
            }
        }
        // compute from current buffer
#pragma unroll
        for (int k = 0; k < BK; k++) {
            float a[8], b[8];
            *(float4*)&a[0] = *(const float4*)&As[cur][k][ty * 8];
            *(float4*)&a[4] = *(const float4*)&As[cur][k][ty * 8 + 4];
            *(float4*)&b[0] = *(const float4*)&Bs[cur][k][tx * 8];
            *(float4*)&b[4] = *(const float4*)&Bs[cur][k][tx * 8 + 4];
#pragma unroll
            for (int i = 0; i < 8; i++)
#pragma unroll
                for (int j = 0; j < 8; j++)
                    acc[i][j] = fmaf(a[i], b[j], acc[i][j]);
        }
        if (more) {
            const int nxt = cur ^ 1;
#pragma unroll
            for (int p = 0; p < 2; p++) {
                const int r = arow + p * 64;
                As[nxt][acol + 0][r] = pa[p].x;
                As[nxt][acol + 1][r] = pa[p].y;
                As[nxt][acol + 2][r] = pa[p].z;
                As[nxt][acol + 3][r] = pa[p].w;
                *(float4*)&Bs[nxt][brow + p * 8][bcol] = pb[p];
            }
            __syncthreads();
            cur = nxt;
        }
    }

    float bn[8];
#pragma unroll
    for (int j = 0; j < 8; j++) {
        const int n = n0 + tx * 8 + j;
        bn[j] = bias[n] + (wrow ? wrow[n] : 0.f);
    }
#pragma unroll
    for (int i = 0; i < 8; i++) {
        const int m = m0 + ty * 8 + i;
        if (m < M) {
            float v[8];
#pragma unroll
            for (int j = 0; j < 8; j++) {
                v[j] = acc[i][j] + bn[j];
                if (do_relu) v[j] = fmaxf(v[j], 0.f);
            }
            float* cp = C + (size_t)m * N + n0 + tx * 8;
            *(float4*)cp       = *(float4*)&v[0];
            *(float4*)(cp + 4) = *(float4*)&v[4];
        }
    }
}

// ---------------- 64x64 SGEMM (for N=64 output: pW) -------------------------
#define TM 64
#define TN 64
#define TK 16
#define SST 72

__global__ __launch_bounds__(256) void gemm64_kernel(
    const float* __restrict__ A, const float* __restrict__ W,
    const float* __restrict__ bias, const float* __restrict__ wrow,
    float* __restrict__ C, int M, int N, int K, int do_relu)
{
    __shared__ float As[TK][SST];
    __shared__ float Bs[TK][SST];
    const int tid = threadIdx.x;
    const int tx  = tid & 15;
    const int ty  = tid >> 4;
    const int m0  = blockIdx.y * TM;
    const int n0  = blockIdx.x * TN;

    const int arow = tid >> 2;
    const int acol = (tid & 3) << 2;
    const int brow = tid >> 4;
    const int bcol = (tid & 15) << 2;

    float acc[4][4] = {{0.f,0.f,0.f,0.f},{0.f,0.f,0.f,0.f},
                       {0.f,0.f,0.f,0.f},{0.f,0.f,0.f,0.f}};

    for (int k0 = 0; k0 < K; k0 += TK) {
        float4 av = make_float4(0.f, 0.f, 0.f, 0.f);
        if (m0 + arow < M)
            av = *(const float4*)(A + (size_t)(m0 + arow) * K + k0 + acol);
        As[acol + 0][arow] = av.x;
        As[acol + 1][arow] = av.y;
        As[acol + 2][arow] = av.z;
        As[acol + 3][arow] = av.w;
        *(float4*)&Bs[brow][bcol] =
            *(const float4*)(W + (size_t)(k0 + brow) * N + n0 + bcol);
        __syncthreads();
#pragma unroll
        for (int k = 0; k < TK; k++) {
            float4 a = *(const float4*)&As[k][ty << 2];
            float4 b = *(const float4*)&Bs[k][tx << 2];
            acc[0][0] = fmaf(a.x, b.x, acc[0][0]);
            acc[0][1] = fmaf(a.x, b.y, acc[0][1]);
            acc[0][2] = fmaf(a.x, b.z, acc[0][2]);
            acc[0][3] = fmaf(a.x, b.w, acc[0][3]);
            acc[1][0] = fmaf(a.y, b.x, acc[1][0]);
            acc[1][1] = fmaf(a.y, b.y, acc[1][1]);
            acc[1][2] = fmaf(a.y, b.z, acc[1][2]);
            acc[1][3] = fmaf(a.y, b.w, acc[1][3]);
            acc[2][0] = fmaf(a.z, b.x, acc[2][0]);
            acc[2][1] = fmaf(a.z, b.y, acc[2][1]);
            acc[2][2] = fmaf(a.z, b.z, acc[2][2]);
            acc[2][3] = fmaf(a.z, b.w, acc[2][3]);
            acc[3][0] = fmaf(a.w, b.x, acc[3][0]);
            acc[3][1] = fmaf(a.w, b.y, acc[3][1]);
            acc[3][2] = fmaf(a.w, b.z, acc[3][2]);
            acc[3][3] = fmaf(a.w, b.w, acc[3][3]);
        }
        __syncthreads();
    }

    float bn[4];
#pragma unroll
    for (int j = 0; j < 4; j++) {
        int n = n0 + (tx << 2) + j;
        bn[j] = bias[n] + (wrow ? wrow[n] : 0.f);
    }
#pragma unroll
    for (int i = 0; i < 4; i++) {
        int m = m0 + (ty << 2) + i;
        if (m < M) {
            float4 v;
            v.x = acc[i][0] + bn[0];
            v.y = acc[i][1] + bn[1];
            v.z = acc[i][2] + bn[2];
            v.w = acc[i][3] + bn[3];
            if (do_relu) {
                v.x = fmaxf(v.x, 0.f); v.y = fmaxf(v.y, 0.f);
                v.z = fmaxf(v.z, 0.f); v.w = fmaxf(v.w, 0.f);
            }
            *(float4*)(C + (size_t)m * N + n0 + (tx << 2)) = v;
        }
    }
}

// ---------------- edge kernel -----------------------------------------------
__global__ __launch_bounds__(256) void edge_kernel(
    const float* __restrict__ emb_new,
    const float* __restrict__ emb_new2,
    const int*   __restrict__ edge_nodes,
    const int*   __restrict__ edge_size,
    const int*   __restrict__ node_degree,
    const float* __restrict__ global_emb,
    const float* __restrict__ qW,
    const float* __restrict__ qb,
    float*       __restrict__ accum)
{
    __shared__ float s_t[4][RANK];
    __shared__ float s_h[4][RANK];
    __shared__ float sge[RANK];
    const int tid = threadIdx.x;
    const int s   = tid >> 6;     // slot 0..3
    const int j   = tid & 63;     // rank index

    float qw[RANK];
#pragma unroll
    for (int jj = 0; jj < RANK; jj++) qw[jj] = qW[jj * OUT_DIM + tid];
    const float qbc = qb[tid];
    if (tid < RANK) sge[tid] = global_emb[tid];
    __syncthreads();

    for (int e = blockIdx.x; e < N_EDGES; e += gridDim.x) {
        const int4 nd = ((const int4*)edge_nodes)[e];
        const int sz = edge_size[e];
        const int myn = (s == 0) ? nd.x : (s == 1) ? nd.y : (s == 2) ? nd.z : nd.w;

        // phase 1: t_{s,j} into smem (all 256 threads in parallel)
        float tval = 1.f;
        if (s < sz) {
            const float d  = (float)node_degree[myn];
            const float sc = (sz <= 3) ? cbrtf(d) : sqrtf(sqrtf(d));
            tval = sc * emb_new[(size_t)myn * RANK + j];
        }
        s_t[s][j] = tval;

        // r2 = relu(sum emb_new2[nodes]) for output col tid
        float r2 = emb_new2[(size_t)nd.x * OUT_DIM + tid]
                 + emb_new2[(size_t)nd.y * OUT_DIM + tid];
        if (sz > 2) r2 += emb_new2[(size_t)nd.z * OUT_DIM + tid];
        if (sz > 3) r2 += emb_new2[(size_t)nd.w * OUT_DIM + tid];
        r2 = fmaxf(r2, 0.f);
        __syncthreads();

        // phase 2: h_{s,j} = tanh(prod_{r!=s} t_r * gf)
        if (s < sz) {
            const int   kk   = 4 - sz;
            const float ge   = sge[j];
            const float invf = (sz == 2) ? 1.f : (sz == 3) ? 0.5f : (1.f / 6.f);
            float p = invf * ((kk == 0) ? 1.f : (kk == 1) ? ge : ge * ge);
#pragma unroll
            for (int r = 0; r < 4; r++)
                if (r != s) p *= s_t[r][j];
            s_h[s][j] = tanh_fast(p);
        }
        __syncthreads();

        // phase 3: per-slot matvec h @ qW (qW col resident in regs) + atomics
        auto slot = [&](const float* hrow, int node) {
            const float4* h4 = (const float4*)hrow;
            float a = qbc;
#pragma unroll
            for (int jj = 0; jj < 16; jj++) {
                float4 hv = h4[jj];
                a = fmaf(hv.x, qw[4 * jj + 0], a);
                a = fmaf(hv.y, qw[4 * jj + 1], a);
                a = fmaf(hv.z, qw[4 * jj + 2], a);
                a = fmaf(hv.w, qw[4 * jj + 3], a);
            }
            atomicAdd(&accum[(size_t)node * OUT_DIM + tid], a + r2);
        };
        slot(s_h[0], nd.x);
        slot(s_h[1], nd.y);
        if (sz > 2) slot(s_h[2], nd.z);
        if (sz > 3) slot(s_h[3], nd.w);

        __syncthreads();   // protect smem reuse next edge
    }
}

// ---------------- helpers ----------------------------------------------------
__global__ void zero_kernel(float* __restrict__ p, int n)
{
    int i = blockIdx.x * blockDim.x + threadIdx.x;
    if (i < n) p[i] = 0.f;
}

__global__ void finalize_kernel(const float* __restrict__ accum,
                                const int*   __restrict__ node_degree,
                                float*       __restrict__ out)
{
    int idx = blockIdx.x * blockDim.x + threadIdx.x;
    if (idx < N_NODES * OUT_DIM) {
        int node = idx >> 8;   // OUT_DIM == 256
        float v = accum[idx] / (float)node_degree[node];
        out[idx] += fmaxf(v, 0.f);   // out already holds the relu residual
    }
}

// ---------------- launch -----------------------------------------------------
extern "C" void kernel_launch(void* const* d_in, const int* in_sizes, int n_in,
                              void* d_out, int out_size)
{
    (void)in_sizes; (void)n_in; (void)out_size;
    const float* embedding  = (const float*)d_in[0];
    const float* global_emb = (const float*)d_in[1];
    const float* pW   = (const float*)d_in[2];
    const float* pb   = (const float*)d_in[3];
    const float* qW   = (const float*)d_in[4];
    const float* qb   = (const float*)d_in[5];
    const float* p2W1 = (const float*)d_in[6];
    const float* p2b1 = (const float*)d_in[7];
    const float* p2W2 = (const float*)d_in[8];
    const float* p2b2 = (const float*)d_in[9];
    const float* aW   = (const float*)d_in[10];
    const float* ab   = (const float*)d_in[11];
    const int* edge_nodes  = (const int*)d_in[12];
    // d_in[13] = edge_mask (bool) — unused: mask[s] == (s < edge_size)
    const int* edge_size   = (const int*)d_in[14];
    const int* node_degree = (const int*)d_in[15];
    float* out = (float*)d_out;

    float *emb_new, *hid, *emb_new2, *acc;
    cudaGetSymbolAddress((void**)&emb_new,  g_emb_new);
    cudaGetSymbolAddress((void**)&hid,      g_hid);
    cudaGetSymbolAddress((void**)&emb_new2, g_emb_new2);
    cudaGetSymbolAddress((void**)&acc,      g_acc);

    dim3 blk(256);
    const int mby64  = (N_NODES + TM - 1) / TM;   // 469
    const int mby128 = (N_NODES + BM - 1) / BM;   // 235

    // emb_new = embedding @ pW[:256] + pW[256] + pb
    gemm64_kernel<<<dim3(RANK / TN, mby64), blk>>>(
        embedding, pW, pb, pW + (size_t)FEAT * RANK,
        emb_new, N_NODES, RANK, FEAT, 0);
    // hid = relu(embedding @ p2W1[:256] + p2W1[256] + p2b1)
    gemm128_kernel<<<dim3(HID / BN, mby128), blk>>>(
        embedding, p2W1, p2b1, p2W1 + (size_t)FEAT * HID,
        hid, N_NODES, HID, FEAT, 1);
    // emb_new2 = hid @ p2W2 + p2b2
    gemm128_kernel<<<dim3(OUT_DIM / BN, mby128), blk>>>(
        hid, p2W2, p2b2, nullptr,
        emb_new2, N_NODES, OUT_DIM, HID, 0);
    // residual = relu(embedding @ aW[:256] + aW[256] + ab) -> d_out
    gemm128_kernel<<<dim3(OUT_DIM / BN, mby128), blk>>>(
        embedding, aW, ab, aW + (size_t)FEAT * OUT_DIM,
        out, N_NODES, OUT_DIM, FEAT, 1);

    zero_kernel<<<(N_NODES * OUT_DIM + 255) / 256, blk>>>(acc, N_NODES * OUT_DIM);

    edge_kernel<<<1480, blk>>>(emb_new, emb_new2, edge_nodes, edge_size,
                               node_degree, global_emb, qW, qb, acc);

    finalize_kernel<<<(N_NODES * OUT_DIM + 255) / 256, blk>>>(acc, node_degree, out);
}

// round 4
// speedup vs baseline: 1.8318x; 1.8318x over previous
#include <cuda_runtime.h>
#include <math.h>
#include <stdint.h>

#define N_NODES 30000
#define N_EDGES 60000
#define FEAT    256
#define HID     1024
#define OUT_DIM 256
#define RANK    64

// ---------------- scratch (static device globals; no runtime allocation) ----
__device__ float g_emb_new [(size_t)N_NODES * RANK];
__device__ float g_hid     [(size_t)N_NODES * HID];
__device__ float g_emb_new2[(size_t)N_NODES * OUT_DIM];
__device__ float g_acc     [(size_t)N_NODES * OUT_DIM];

__device__ __forceinline__ float tanh_fast(float x)
{
    float y;
    asm("tanh.approx.f32 %0, %1;" : "=f"(y) : "f"(x));
    return y;
}

__device__ __forceinline__ float to_tf32(float x)
{
    uint32_t u;
    asm("cvt.rna.tf32.f32 %0, %1;" : "=r"(u) : "f"(x));
    return __uint_as_float(u);
}

__device__ __forceinline__ void mma_tf32(float d[4], const uint32_t a[4],
                                         const uint32_t b[2])
{
    asm("mma.sync.aligned.m16n8k8.row.col.f32.tf32.tf32.f32 "
        "{%0,%1,%2,%3}, {%4,%5,%6,%7}, {%8,%9}, {%0,%1,%2,%3};"
        : "+f"(d[0]), "+f"(d[1]), "+f"(d[2]), "+f"(d[3])
        : "r"(a[0]), "r"(a[1]), "r"(a[2]), "r"(a[3]),
          "r"(b[0]), "r"(b[1]));
}

// ============ tf32 tensor-core GEMM: C = act(A @ W[:K] + wrow + bias) =======
// Block tile 128x128, BK=32. 8 warps = 2 (m) x 4 (n); warp tile 64x32.
// A: MxK row-major (fp32), W: (K(+1))xN row-major. N % 128 == 0, K % 32 == 0.
__global__ __launch_bounds__(256) void gemm_tf32_kernel(
    const float* __restrict__ A, const float* __restrict__ W,
    const float* __restrict__ bias, const float* __restrict__ wrow,
    float* __restrict__ C, int M, int N, int K, int do_relu)
{
    __shared__ float As[128][36];   // padded: frag loads conflict-free
    __shared__ float Bs[32][132];
    const int tid    = threadIdx.x;
    const int lane   = tid & 31;
    const int w      = tid >> 5;
    const int warp_m = w & 1;       // 0..1 -> 64 rows
    const int warp_n = w >> 1;      // 0..3 -> 32 cols
    const int g      = lane >> 2;   // 0..7
    const int tg     = lane & 3;    // 0..3
    const int m0     = blockIdx.y * 128;
    const int n0     = blockIdx.x * 128;

    float d[4][4][4];
#pragma unroll
    for (int i = 0; i < 4; i++)
#pragma unroll
        for (int j = 0; j < 4; j++)
#pragma unroll
            for (int c = 0; c < 4; c++) d[i][j][c] = 0.f;

    // gmem->smem assignment (per-phase conflict-free stores):
    // A: warp w -> rows w*16 + (lane>>1), k-half (lane&1)*16, 4 float4 each
    const int a_r = w * 16 + (lane >> 1);
    const int a_k = (lane & 1) * 16;
    // B: warp w -> k-rows w + 8p, lane -> 4 cols each
    const int b_n = lane * 4;

    for (int k0 = 0; k0 < K; k0 += 32) {
        // ---- load A tile ----
        {
            const bool ok = (m0 + a_r) < M;
            const float* ap = A + (size_t)(m0 + a_r) * K + k0 + a_k;
#pragma unroll
            for (int c = 0; c < 4; c++) {
                float4 v = make_float4(0.f, 0.f, 0.f, 0.f);
                if (ok) v = *(const float4*)(ap + 4 * c);
                As[a_r][a_k + 4 * c + 0] = to_tf32(v.x);
                As[a_r][a_k + 4 * c + 1] = to_tf32(v.y);
                As[a_r][a_k + 4 * c + 2] = to_tf32(v.z);
                As[a_r][a_k + 4 * c + 3] = to_tf32(v.w);
            }
        }
        // ---- load B tile ----
#pragma unroll
        for (int p = 0; p < 4; p++) {
            const int kk = w + p * 8;
            float4 v = *(const float4*)(W + (size_t)(k0 + kk) * N + n0 + b_n);
            Bs[kk][b_n + 0] = to_tf32(v.x);
            Bs[kk][b_n + 1] = to_tf32(v.y);
            Bs[kk][b_n + 2] = to_tf32(v.z);
            Bs[kk][b_n + 3] = to_tf32(v.w);
        }
        __syncthreads();

#pragma unroll
        for (int ks = 0; ks < 32; ks += 8) {
            uint32_t af[4][4], bf[4][2];
#pragma unroll
            for (int mg = 0; mg < 4; mg++) {
                const int r = warp_m * 64 + mg * 16 + g;
                af[mg][0] = __float_as_uint(As[r    ][ks + tg    ]);
                af[mg][1] = __float_as_uint(As[r + 8][ks + tg    ]);
                af[mg][2] = __float_as_uint(As[r    ][ks + tg + 4]);
                af[mg][3] = __float_as_uint(As[r + 8][ks + tg + 4]);
            }
#pragma unroll
            for (int ng = 0; ng < 4; ng++) {
                const int cc = warp_n * 32 + ng * 8 + g;
                bf[ng][0] = __float_as_uint(Bs[ks + tg    ][cc]);
                bf[ng][1] = __float_as_uint(Bs[ks + tg + 4][cc]);
            }
#pragma unroll
            for (int mg = 0; mg < 4; mg++)
#pragma unroll
                for (int ng = 0; ng < 4; ng++)
                    mma_tf32(d[mg][ng], af[mg], bf[ng]);
        }
        __syncthreads();
    }

    // ---- epilogue: d-frag -> C with bias(+wrow) and optional relu ----
#pragma unroll
    for (int mg = 0; mg < 4; mg++) {
        const int r0 = m0 + warp_m * 64 + mg * 16 + g;
#pragma unroll
        for (int ng = 0; ng < 4; ng++) {
            const int col = n0 + warp_n * 32 + ng * 8 + tg * 2;
            float b0 = bias[col]     + (wrow ? wrow[col]     : 0.f);
            float b1 = bias[col + 1] + (wrow ? wrow[col + 1] : 0.f);
            float v0 = d[mg][ng][0] + b0;
            float v1 = d[mg][ng][1] + b1;
            float v2 = d[mg][ng][2] + b0;
            float v3 = d[mg][ng][3] + b1;
            if (do_relu) {
                v0 = fmaxf(v0, 0.f); v1 = fmaxf(v1, 0.f);
                v2 = fmaxf(v2, 0.f); v3 = fmaxf(v3, 0.f);
            }
            if (r0 < M)
                *(float2*)(C + (size_t)r0 * N + col) = make_float2(v0, v1);
            if (r0 + 8 < M)
                *(float2*)(C + (size_t)(r0 + 8) * N + col) = make_float2(v2, v3);
        }
    }
}

// ---------------- 64x64 fp32 SGEMM (pW only: accuracy-critical path) --------
#define TM 64
#define TN 64
#define TK 16
#define SST 72

__global__ __launch_bounds__(256) void gemm64_kernel(
    const float* __restrict__ A, const float* __restrict__ W,
    const float* __restrict__ bias, const float* __restrict__ wrow,
    float* __restrict__ C, int M, int N, int K, int do_relu)
{
    __shared__ float As[TK][SST];
    __shared__ float Bs[TK][SST];
    const int tid = threadIdx.x;
    const int tx  = tid & 15;
    const int ty  = tid >> 4;
    const int m0  = blockIdx.y * TM;
    const int n0  = blockIdx.x * TN;

    const int arow = tid >> 2;
    const int acol = (tid & 3) << 2;
    const int brow = tid >> 4;
    const int bcol = (tid & 15) << 2;

    float acc[4][4] = {{0.f,0.f,0.f,0.f},{0.f,0.f,0.f,0.f},
                       {0.f,0.f,0.f,0.f},{0.f,0.f,0.f,0.f}};

    for (int k0 = 0; k0 < K; k0 += TK) {
        float4 av = make_float4(0.f, 0.f, 0.f, 0.f);
        if (m0 + arow < M)
            av = *(const float4*)(A + (size_t)(m0 + arow) * K + k0 + acol);
        As[acol + 0][arow] = av.x;
        As[acol + 1][arow] = av.y;
        As[acol + 2][arow] = av.z;
        As[acol + 3][arow] = av.w;
        *(float4*)&Bs[brow][bcol] =
            *(const float4*)(W + (size_t)(k0 + brow) * N + n0 + bcol);
        __syncthreads();
#pragma unroll
        for (int k = 0; k < TK; k++) {
            float4 a = *(const float4*)&As[k][ty << 2];
            float4 b = *(const float4*)&Bs[k][tx << 2];
            acc[0][0] = fmaf(a.x, b.x, acc[0][0]);
            acc[0][1] = fmaf(a.x, b.y, acc[0][1]);
            acc[0][2] = fmaf(a.x, b.z, acc[0][2]);
            acc[0][3] = fmaf(a.x, b.w, acc[0][3]);
            acc[1][0] = fmaf(a.y, b.x, acc[1][0]);
            acc[1][1] = fmaf(a.y, b.y, acc[1][1]);
            acc[1][2] = fmaf(a.y, b.z, acc[1][2]);
            acc[1][3] = fmaf(a.y, b.w, acc[1][3]);
            acc[2][0] = fmaf(a.z, b.x, acc[2][0]);
            acc[2][1] = fmaf(a.z, b.y, acc[2][1]);
            acc[2][2] = fmaf(a.z, b.z, acc[2][2]);
            acc[2][3] = fmaf(a.z, b.w, acc[2][3]);
            acc[3][0] = fmaf(a.w, b.x, acc[3][0]);
            acc[3][1] = fmaf(a.w, b.y, acc[3][1]);
            acc[3][2] = fmaf(a.w, b.z, acc[3][2]);
            acc[3][3] = fmaf(a.w, b.w, acc[3][3]);
        }
        __syncthreads();
    }

    float bn[4];
#pragma unroll
    for (int j = 0; j < 4; j++) {
        int n = n0 + (tx << 2) + j;
        bn[j] = bias[n] + (wrow ? wrow[n] : 0.f);
    }
#pragma unroll
    for (int i = 0; i < 4; i++) {
        int m = m0 + (ty << 2) + i;
        if (m < M) {
            float4 v;
            v.x = acc[i][0] + bn[0];
            v.y = acc[i][1] + bn[1];
            v.z = acc[i][2] + bn[2];
            v.w = acc[i][3] + bn[3];
            if (do_relu) {
                v.x = fmaxf(v.x, 0.f); v.y = fmaxf(v.y, 0.f);
                v.z = fmaxf(v.z, 0.f); v.w = fmaxf(v.w, 0.f);
            }
            *(float4*)(C + (size_t)m * N + n0 + (tx << 2)) = v;
        }
    }
}

// ---------------- edge kernel -----------------------------------------------
__global__ __launch_bounds__(256) void edge_kernel(
    const float* __restrict__ emb_new,
    const float* __restrict__ emb_new2,
    const int*   __restrict__ edge_nodes,
    const int*   __restrict__ edge_size,
    const int*   __restrict__ node_degree,
    const float* __restrict__ global_emb,
    const float* __restrict__ qW,
    const float* __restrict__ qb,
    float*       __restrict__ accum)
{
    __shared__ float s_t[4][RANK];
    __shared__ float s_h[4][RANK];
    __shared__ float sge[RANK];
    const int tid = threadIdx.x;
    const int s   = tid >> 6;     // slot 0..3
    const int j   = tid & 63;     // rank index

    float qw[RANK];
#pragma unroll
    for (int jj = 0; jj < RANK; jj++) qw[jj] = qW[jj * OUT_DIM + tid];
    const float qbc = qb[tid];
    if (tid < RANK) sge[tid] = global_emb[tid];
    __syncthreads();

    for (int e = blockIdx.x; e < N_EDGES; e += gridDim.x) {
        const int4 nd = ((const int4*)edge_nodes)[e];
        const int sz = edge_size[e];
        const int myn = (s == 0) ? nd.x : (s == 1) ? nd.y : (s == 2) ? nd.z : nd.w;

        float tval = 1.f;
        if (s < sz) {
            const float d  = (float)node_degree[myn];
            const float sc = (sz <= 3) ? cbrtf(d) : sqrtf(sqrtf(d));
            tval = sc * emb_new[(size_t)myn * RANK + j];
        }
        s_t[s][j] = tval;

        float r2 = emb_new2[(size_t)nd.x * OUT_DIM + tid]
                 + emb_new2[(size_t)nd.y * OUT_DIM + tid];
        if (sz > 2) r2 += emb_new2[(size_t)nd.z * OUT_DIM + tid];
        if (sz > 3) r2 += emb_new2[(size_t)nd.w * OUT_DIM + tid];
        r2 = fmaxf(r2, 0.f);
        __syncthreads();

        if (s < sz) {
            const int   kk   = 4 - sz;
            const float ge   = sge[j];
            const float invf = (sz == 2) ? 1.f : (sz == 3) ? 0.5f : (1.f / 6.f);
            float p = invf * ((kk == 0) ? 1.f : (kk == 1) ? ge : ge * ge);
#pragma unroll
            for (int r = 0; r < 4; r++)
                if (r != s) p *= s_t[r][j];
            s_h[s][j] = tanh_fast(p);
        }
        __syncthreads();

        auto slot = [&](const float* hrow, int node) {
            const float4* h4 = (const float4*)hrow;
            float a = qbc;
#pragma unroll
            for (int jj = 0; jj < 16; jj++) {
                float4 hv = h4[jj];
                a = fmaf(hv.x, qw[4 * jj + 0], a);
                a = fmaf(hv.y, qw[4 * jj + 1], a);
                a = fmaf(hv.z, qw[4 * jj + 2], a);
                a = fmaf(hv.w, qw[4 * jj + 3], a);
            }
            atomicAdd(&accum[(size_t)node * OUT_DIM + tid], a + r2);
        };
        slot(s_h[0], nd.x);
        slot(s_h[1], nd.y);
        if (sz > 2) slot(s_h[2], nd.z);
        if (sz > 3) slot(s_h[3], nd.w);

        __syncthreads();
    }
}

// ---------------- helpers ----------------------------------------------------
__global__ void zero_kernel(float* __restrict__ p, int n)
{
    int i = blockIdx.x * blockDim.x + threadIdx.x;
    if (i < n) p[i] = 0.f;
}

__global__ void finalize_kernel(const float* __restrict__ accum,
                                const int*   __restrict__ node_degree,
                                float*       __restrict__ out)
{
    int idx = blockIdx.x * blockDim.x + threadIdx.x;
    if (idx < N_NODES * OUT_DIM) {
        int node = idx >> 8;   // OUT_DIM == 256
        float v = accum[idx] / (float)node_degree[node];
        out[idx] += fmaxf(v, 0.f);   // out already holds the relu residual
    }
}

// ---------------- launch -----------------------------------------------------
extern "C" void kernel_launch(void* const* d_in, const int* in_sizes, int n_in,
                              void* d_out, int out_size)
{
    (void)in_sizes; (void)n_in; (void)out_size;
    const float* embedding  = (const float*)d_in[0];
    const float* global_emb = (const float*)d_in[1];
    const float* pW   = (const float*)d_in[2];
    const float* pb   = (const float*)d_in[3];
    const float* qW   = (const float*)d_in[4];
    const float* qb   = (const float*)d_in[5];
    const float* p2W1 = (const float*)d_in[6];
    const float* p2b1 = (const float*)d_in[7];
    const float* p2W2 = (const float*)d_in[8];
    const float* p2b2 = (const float*)d_in[9];
    const float* aW   = (const float*)d_in[10];
    const float* ab   = (const float*)d_in[11];
    const int* edge_nodes  = (const int*)d_in[12];
    // d_in[13] = edge_mask (bool) — unused: mask[s] == (s < edge_size)
    const int* edge_size   = (const int*)d_in[14];
    const int* node_degree = (const int*)d_in[15];
    float* out = (float*)d_out;

    float *emb_new, *hid, *emb_new2, *acc;
    cudaGetSymbolAddress((void**)&emb_new,  g_emb_new);
    cudaGetSymbolAddress((void**)&hid,      g_hid);
    cudaGetSymbolAddress((void**)&emb_new2, g_emb_new2);
    cudaGetSymbolAddress((void**)&acc,      g_acc);

    dim3 blk(256);
    const int mby64  = (N_NODES + TM - 1) / TM;    // 469
    const int mby128 = (N_NODES + 127) / 128;      // 235

    // emb_new = embedding @ pW[:256] + pW[256] + pb   (fp32: accuracy-critical)
    gemm64_kernel<<<dim3(RANK / TN, mby64), blk>>>(
        embedding, pW, pb, pW + (size_t)FEAT * RANK,
        emb_new, N_NODES, RANK, FEAT, 0);
    // hid = relu(embedding @ p2W1[:256] + p2W1[256] + p2b1)  (tf32 tensor)
    gemm_tf32_kernel<<<dim3(HID / 128, mby128), blk>>>(
        embedding, p2W1, p2b1, p2W1 + (size_t)FEAT * HID,
        hid, N_NODES, HID, FEAT, 1);
    // emb_new2 = hid @ p2W2 + p2b2  (tf32 tensor)
    gemm_tf32_kernel<<<dim3(OUT_DIM / 128, mby128), blk>>>(
        hid, p2W2, p2b2, nullptr,
        emb_new2, N_NODES, OUT_DIM, HID, 0);
    // residual = relu(embedding @ aW[:256] + aW[256] + ab) -> d_out  (tf32)
    gemm_tf32_kernel<<<dim3(OUT_DIM / 128, mby128), blk>>>(
        embedding, aW, ab, aW + (size_t)FEAT * OUT_DIM,
        out, N_NODES, OUT_DIM, FEAT, 1);

    zero_kernel<<<(N_NODES * OUT_DIM + 255) / 256, blk>>>(acc, N_NODES * OUT_DIM);

    edge_kernel<<<1480, blk>>>(emb_new, emb_new2, edge_nodes, edge_size,
                               node_degree, global_emb, qW, qb, acc);

    finalize_kernel<<<(N_NODES * OUT_DIM + 255) / 256, blk>>>(acc, node_degree, out);
}